// round 1
// baseline (speedup 1.0000x reference)
#include <cuda_runtime.h>
#include <cstdint>
#include <cstddef>

// ---------------------------------------------------------------------------
// Who2com forward, fp32 baseline.
//   bevs (32,5,256,16,16) -> 5x conv3x3+affine+relu -> feats (160,4096)
//   -> key/query MLPs -> attention (5x5 per b) -> softmax -> fuse weights
//   -> out[b] = sum_k w[b,k] * bevs[b,k]   (mean over queries folded in)
// ---------------------------------------------------------------------------

// Scratch (device globals; no allocation allowed)
__device__ float g_b1[(size_t)160 * 512 * 16 * 16];  // conv1 out
__device__ float g_b2[(size_t)160 * 256 * 16 * 16];  // conv2 out
__device__ float g_b3[(size_t)160 * 256 * 8 * 8];    // conv3 out
__device__ float g_b4[(size_t)160 * 256 * 8 * 8];    // conv4 out
__device__ float g_feat[(size_t)160 * 4096];         // conv5 out = feats
__device__ float g_m1[160 * 256];
__device__ float g_m2[160 * 128];
__device__ float g_keys[160 * 1024];
__device__ float g_qrys[160 * 32];
__device__ float g_qq[160 * 1024];
__device__ float g_wf[32 * 5];

// ---------------------------------------------------------------------------
// Direct 3x3 conv + folded-BN affine + ReLU.
// Per block: one image, BCO=TCO*16 output channels, all HO*WO pixels.
// Per thread: 4 pixels x 16 channels = 64 fp32 accumulators.
// tid = ty + tx*TCO  (ty: co group, tx: pixel group) so warps replicate over
// co -> input LDS broadcasts, weight LDS.128 conflict-free.
// ---------------------------------------------------------------------------
template <int CIN, int COUT, int HIN, int WIN, int STRIDE, int TPX, int TCO>
__global__ void __launch_bounds__(TPX * TCO)
conv3x3_kernel(const float* __restrict__ in, const float* __restrict__ wgt,
               const float* __restrict__ scale, const float* __restrict__ shift,
               float* __restrict__ out)
{
    constexpr int HO  = (HIN - 1) / STRIDE + 1;
    constexpr int WO  = (WIN - 1) / STRIDE + 1;
    constexpr int HP  = HIN + 2, WP = WIN + 2;
    constexpr int BCI = 8;
    constexpr int BCO = TCO * 16;
    constexpr int NT  = TPX * TCO;

    __shared__ float sIn[BCI][HP * WP];
    __shared__ __align__(16) float sW[BCI * 9][BCO + 4];  // +4 pad: store conflicts 4-way

    const int n   = blockIdx.y;
    const int co0 = blockIdx.x * BCO;
    const int tid = threadIdx.x;
    const int ty  = tid % TCO;
    const int tx  = tid / TCO;
    const int p0  = tx * 4;          // 4 consecutive pixels, same output row
    const int oh  = p0 / WO;
    const int ow0 = p0 % WO;

    float acc[4][16];
#pragma unroll
    for (int p = 0; p < 4; p++)
#pragma unroll
        for (int c = 0; c < 16; c++) acc[p][c] = 0.f;

    const float* inN = in + (size_t)n * CIN * HIN * WIN;

    for (int cb = 0; cb < CIN; cb += BCI) {
        // cooperative input tile (BCI channels, zero halo)
        for (int i = tid; i < BCI * HP * WP; i += NT) {
            int ci  = i / (HP * WP);
            int rem = i - ci * (HP * WP);
            int hp  = rem / WP;
            int wp  = rem - hp * WP;
            int h = hp - 1, w = wp - 1;
            float v = 0.f;
            if ((unsigned)h < (unsigned)HIN && (unsigned)w < (unsigned)WIN)
                v = inN[(size_t)(cb + ci) * (HIN * WIN) + h * WIN + w];
            sIn[ci][rem] = v;
        }
        // cooperative weight tile, k-fastest in global (coalesced)
        for (int i = tid; i < BCI * 9 * BCO; i += NT) {
            int col = i / (BCI * 9);
            int rk  = i - col * (BCI * 9);             // ci*9 + k
            sW[rk][col] =
                wgt[((size_t)(co0 + col) * CIN + (cb + rk / 9)) * 9 + (rk % 9)];
        }
        __syncthreads();

#pragma unroll 1
        for (int ci = 0; ci < BCI; ci++) {
#pragma unroll
            for (int kh = 0; kh < 3; kh++) {
#pragma unroll
                for (int kw = 0; kw < 3; kw++) {
                    float iv[4];
#pragma unroll
                    for (int p = 0; p < 4; p++)
                        iv[p] = sIn[ci][(oh * STRIDE + kh) * WP +
                                        (ow0 + p) * STRIDE + kw];
                    const float* wrow = &sW[ci * 9 + kh * 3 + kw][ty * 16];
                    float4 w0 = *(const float4*)(wrow + 0);
                    float4 w1 = *(const float4*)(wrow + 4);
                    float4 w2 = *(const float4*)(wrow + 8);
                    float4 w3 = *(const float4*)(wrow + 12);
                    float wv[16] = {w0.x, w0.y, w0.z, w0.w, w1.x, w1.y, w1.z, w1.w,
                                    w2.x, w2.y, w2.z, w2.w, w3.x, w3.y, w3.z, w3.w};
#pragma unroll
                    for (int c = 0; c < 16; c++)
#pragma unroll
                        for (int p = 0; p < 4; p++)
                            acc[p][c] = fmaf(iv[p], wv[c], acc[p][c]);
                }
            }
        }
        __syncthreads();
    }

    const int cobase = co0 + ty * 16;
#pragma unroll
    for (int c = 0; c < 16; c++) {
        float s = scale[cobase + c];
        float t = shift[cobase + c];
        size_t ob = ((size_t)n * COUT + cobase + c) * (HO * WO) + oh * WO + ow0;
#pragma unroll
        for (int p = 0; p < 4; p++) {
            float v = fmaf(acc[p][c], s, t);
            out[ob + p] = v > 0.f ? v : 0.f;
        }
    }
}

// ---------------------------------------------------------------------------
// Y[m,n] = act( X[m,:] . W[n,:] + bias[n] ) — one warp per output element.
// K must be a multiple of 4 (all our K are).
// ---------------------------------------------------------------------------
__global__ void warpdot_kernel(const float* __restrict__ X, const float* __restrict__ W,
                               const float* __restrict__ bias, float* __restrict__ Y,
                               int M, int N, int K, int doRelu)
{
    int gw   = (blockIdx.x * blockDim.x + threadIdx.x) >> 5;
    int lane = threadIdx.x & 31;
    if (gw >= M * N) return;
    int m = gw / N, n = gw - m * N;
    const float4* x = (const float4*)(X + (size_t)m * K);
    const float4* w = (const float4*)(W + (size_t)n * K);
    float acc = 0.f;
    int K4 = K >> 2;
    for (int k = lane; k < K4; k += 32) {
        float4 a = x[k], b = w[k];
        acc += a.x * b.x + a.y * b.y + a.z * b.z + a.w * b.w;
    }
#pragma unroll
    for (int o = 16; o; o >>= 1) acc += __shfl_xor_sync(0xffffffffu, acc, o);
    if (lane == 0) {
        float v = acc + bias[n];
        if (doRelu) v = fmaxf(v, 0.f);
        Y[(size_t)m * N + n] = v;
    }
}

// ---------------------------------------------------------------------------
// Per-b attention: attn[i,j] = keys[i*32+b] . qq[j*32+b]  (the reference's
// deliberately mismatched (N,B) refactorization), del-diag softmax over the
// compacted key dim, then fuse weights w[b,i] = (1/5) * sum_j final[b,i,j].
// ---------------------------------------------------------------------------
__global__ void attn_kernel(const float* __restrict__ keys, const float* __restrict__ qq,
                            float* __restrict__ wf)
{
    int b = blockIdx.x;
    __shared__ float sA[5][5];
    int warp = threadIdx.x >> 5, lane = threadIdx.x & 31;
    for (int e = warp; e < 25; e += 8) {
        int i = e / 5, j = e - i * 5;
        const float4* kr = (const float4*)(keys + (size_t)(i * 32 + b) * 1024);
        const float4* qr = (const float4*)(qq + (size_t)(j * 32 + b) * 1024);
        float acc = 0.f;
        for (int k = lane; k < 256; k += 32) {
            float4 a = kr[k], c = qr[k];
            acc += a.x * c.x + a.y * c.y + a.z * c.z + a.w * c.w;
        }
#pragma unroll
        for (int o = 16; o; o >>= 1) acc += __shfl_xor_sync(0xffffffffu, acc, o);
        if (lane == 0) sA[i][j] = acc;
    }
    __syncthreads();
    if (threadIdx.x == 0) {
        float w[5] = {0.f, 0.f, 0.f, 0.f, 0.f};
        for (int j = 0; j < 5; j++) {
            float dd[4], mx = -1e30f;
            for (int r = 0; r < 4; r++) {
                dd[r] = (j > r) ? sA[r][j] : sA[r + 1][j];
                mx = fmaxf(mx, dd[r]);
            }
            float s = 0.f;
            for (int r = 0; r < 4; r++) { dd[r] = expf(dd[r] - mx); s += dd[r]; }
            float inv = 1.f / s;
            for (int r = 0; r < 4; r++) {
                int i = (j > r) ? r : r + 1;  // where sm[r,j] lands in `final`
                w[i] += dd[r] * inv;
            }
        }
        for (int i = 0; i < 5; i++) wf[b * 5 + i] = w[i] * 0.2f;
    }
}

// out[b,chw] = sum_k wf[b,k] * bevs[b,k,chw]
__global__ void fuse_kernel(const float* __restrict__ bevs, const float* __restrict__ wf,
                            float* __restrict__ out)
{
    const int CHW = 256 * 16 * 16;
    int idx = blockIdx.x * blockDim.x + threadIdx.x;
    if (idx >= 32 * CHW) return;
    int b   = idx / CHW;
    int chw = idx - b * CHW;
    const float* base = bevs + ((size_t)b * 5) * CHW + chw;
    float acc = 0.f;
#pragma unroll
    for (int k = 0; k < 5; k++) acc += wf[b * 5 + k] * base[(size_t)k * CHW];
    out[idx] = acc;
}

// ---------------------------------------------------------------------------
extern "C" void kernel_launch(void* const* d_in, const int* in_sizes, int n_in,
                              void* d_out, int out_size)
{
    (void)in_sizes; (void)n_in; (void)out_size;
    const float* bevs = (const float*)d_in[0];
    const float *cw[5], *cs[5], *ct[5];
    for (int i = 0; i < 5; i++) {
        cw[i] = (const float*)d_in[1 + 3 * i];
        cs[i] = (const float*)d_in[2 + 3 * i];
        ct[i] = (const float*)d_in[3 + 3 * i];
    }
    const float* kw1 = (const float*)d_in[16]; const float* kb1 = (const float*)d_in[17];
    const float* kw2 = (const float*)d_in[18]; const float* kb2 = (const float*)d_in[19];
    const float* kw3 = (const float*)d_in[20]; const float* kb3 = (const float*)d_in[21];
    const float* qw1 = (const float*)d_in[22]; const float* qb1 = (const float*)d_in[23];
    const float* qw2 = (const float*)d_in[24]; const float* qb2 = (const float*)d_in[25];
    const float* qw3 = (const float*)d_in[26]; const float* qb3 = (const float*)d_in[27];
    const float* aw  = (const float*)d_in[28]; const float* ab  = (const float*)d_in[29];
    float* out = (float*)d_out;

    float *b1, *b2, *b3, *b4, *feat, *m1, *m2, *keys, *qrys, *qq, *wf;
    cudaGetSymbolAddress((void**)&b1, g_b1);
    cudaGetSymbolAddress((void**)&b2, g_b2);
    cudaGetSymbolAddress((void**)&b3, g_b3);
    cudaGetSymbolAddress((void**)&b4, g_b4);
    cudaGetSymbolAddress((void**)&feat, g_feat);
    cudaGetSymbolAddress((void**)&m1, g_m1);
    cudaGetSymbolAddress((void**)&m2, g_m2);
    cudaGetSymbolAddress((void**)&keys, g_keys);
    cudaGetSymbolAddress((void**)&qrys, g_qrys);
    cudaGetSymbolAddress((void**)&qq, g_qq);
    cudaGetSymbolAddress((void**)&wf, g_wf);

    // conv stack (160 images)
    conv3x3_kernel<256, 512, 16, 16, 1, 64, 4><<<dim3(8, 160), 256>>>(bevs, cw[0], cs[0], ct[0], b1);
    conv3x3_kernel<512, 256, 16, 16, 1, 64, 4><<<dim3(4, 160), 256>>>(b1,   cw[1], cs[1], ct[1], b2);
    conv3x3_kernel<256, 256, 16, 16, 2, 16, 8><<<dim3(2, 160), 128>>>(b2,   cw[2], cs[2], ct[2], b3);
    conv3x3_kernel<256, 256,  8,  8, 1, 16, 8><<<dim3(2, 160), 128>>>(b3,   cw[3], cs[3], ct[3], b4);
    conv3x3_kernel<256, 256,  8,  8, 2,  4, 8><<<dim3(2, 160),  32>>>(b4,   cw[4], cs[4], ct[4], feat);

    // MLPs + projection (warp-per-output)
    auto wd = [&](const float* X, const float* W, const float* B, float* Y,
                  int M, int N, int K, int relu) {
        int blocks = (M * N + 7) / 8;
        warpdot_kernel<<<blocks, 256>>>(X, W, B, Y, M, N, K, relu);
    };
    wd(feat, kw1, kb1, m1,   160,  256, 4096, 1);
    wd(m1,   kw2, kb2, m2,   160,  128,  256, 1);
    wd(m2,   kw3, kb3, keys, 160, 1024,  128, 0);
    wd(feat, qw1, qb1, m1,   160,  256, 4096, 1);
    wd(m1,   qw2, qb2, m2,   160,  128,  256, 1);
    wd(m2,   qw3, qb3, qrys, 160,   32,  128, 0);
    wd(qrys, aw,  ab,  qq,   160, 1024,   32, 0);

    attn_kernel<<<32, 256>>>(keys, qq, wf);
    fuse_kernel<<<(32 * 256 * 16 * 16 + 255) / 256, 256>>>(bevs, wf, out);
}

// round 3
// speedup vs baseline: 2.7016x; 2.7016x over previous
#include <cuda_runtime.h>
#include <cuda_bf16.h>
#include <cstdint>
#include <cstddef>

// ===========================================================================
// Who2com forward — split-bf16 mma.sync (HMMA) implicit-GEMM convs + tail.
// Base-ISA tensor ops only (mma.sync + ldmatrix): compiles for plain sm_103.
// ===========================================================================

__device__ __forceinline__ uint32_t smem_to_u32(const void* p) {
    uint32_t a;
    asm("{ .reg .u64 t; cvta.to.shared.u64 t, %1; cvt.u32.u64 %0, t; }"
        : "=r"(a) : "l"(p));
    return a;
}
__device__ __forceinline__ void ldsm_x4(uint32_t (&r)[4], uint32_t addr) {
    asm volatile("ldmatrix.sync.aligned.m8n8.x4.shared.b16 {%0,%1,%2,%3}, [%4];"
                 : "=r"(r[0]), "=r"(r[1]), "=r"(r[2]), "=r"(r[3]) : "r"(addr));
}
__device__ __forceinline__ void mma_bf16(float (&d)[4], const uint32_t (&a)[4],
                                         uint32_t b0, uint32_t b1) {
    asm volatile(
        "mma.sync.aligned.m16n8k16.row.col.f32.bf16.bf16.f32 "
        "{%0,%1,%2,%3}, {%4,%5,%6,%7}, {%8,%9}, {%0,%1,%2,%3};"
        : "+f"(d[0]), "+f"(d[1]), "+f"(d[2]), "+f"(d[3])
        : "r"(a[0]), "r"(a[1]), "r"(a[2]), "r"(a[3]), "r"(b0), "r"(b1));
}
__device__ __forceinline__ uint32_t pack_bf2(__nv_bfloat16 a, __nv_bfloat16 b) {
    __nv_bfloat162 t = __halves2bfloat162(a, b);
    return *reinterpret_cast<uint32_t*>(&t);
}
__device__ __forceinline__ void sts32(uint32_t addr, uint32_t v) {
    asm volatile("st.shared.b32 [%0], %1;" :: "r"(addr), "r"(v) : "memory");
}
__device__ __forceinline__ void sts128(uint32_t addr, uint4 v) {
    asm volatile("st.shared.v4.b32 [%0], {%1,%2,%3,%4};"
                 :: "r"(addr), "r"(v.x), "r"(v.y), "r"(v.z), "r"(v.w) : "memory");
}

// ---------------------------------------------------------------------------
// Scratch (no allocation allowed)
// ---------------------------------------------------------------------------
__device__ float g_b1[(size_t)160 * 512 * 256];
__device__ float g_b2[(size_t)160 * 256 * 256];
__device__ float g_b3[(size_t)160 * 256 * 64];
__device__ float g_b4[(size_t)160 * 256 * 64];
__device__ float g_feat[(size_t)160 * 4096];
__device__ float g_m1[160 * 256];
__device__ float g_m2[160 * 128];
__device__ float g_keys[160 * 1024];
__device__ float g_qrys[160 * 32];
__device__ float g_qq[160 * 1024];
__device__ float g_wf[32 * 5];
// split weights: [co][tap*CIN + ci], hi/lo bf16
__device__ __align__(16) __nv_bfloat16 g_w1h[512 * 2304], g_w1l[512 * 2304];
__device__ __align__(16) __nv_bfloat16 g_w2h[256 * 4608], g_w2l[256 * 4608];
__device__ __align__(16) __nv_bfloat16 g_w3h[256 * 2304], g_w3l[256 * 2304];
__device__ __align__(16) __nv_bfloat16 g_w4h[256 * 2304], g_w4l[256 * 2304];
__device__ __align__(16) __nv_bfloat16 g_w5h[256 * 2304], g_w5l[256 * 2304];

// ---------------------------------------------------------------------------
// Weight prep: src[co][ci][kh][kw] -> hi/lo bf16 at [co][(kh*3+kw)*CIN + ci]
// ---------------------------------------------------------------------------
__global__ void wprep_kernel(const float* __restrict__ w, __nv_bfloat16* __restrict__ hi,
                             __nv_bfloat16* __restrict__ lo, int COUT, int CIN)
{
    int total = COUT * CIN * 9;
    for (int idx = blockIdx.x * blockDim.x + threadIdx.x; idx < total;
         idx += gridDim.x * blockDim.x) {
        int co = idx / (CIN * 9);
        int rem = idx - co * (CIN * 9);
        int ci = rem / 9, tap = rem - ci * 9;
        float v = w[idx];
        __nv_bfloat16 h = __float2bfloat16(v);
        __nv_bfloat16 l = __float2bfloat16(v - __bfloat162float(h));
        size_t d = (size_t)co * (CIN * 9) + tap * CIN + ci;
        hi[d] = h; lo[d] = l;
    }
}

// ---------------------------------------------------------------------------
// Implicit-GEMM conv3x3 (pad=1) + affine + ReLU, split-bf16 mma.sync.
// D[pix, co] = sum_k A[pix,k]*B[co,k], k = tap*CIN + ci.
// Block: 128 M-rows (pixels, possibly several images) x 128 cout, 256 thr.
// smem tiles: 128 x 64 bf16, pitch 72 bf16 (144B, 16B-aligned, ldmatrix-clean)
// ---------------------------------------------------------------------------
static constexpr int SPITCH = 72;            // bf16
static constexpr int SPB    = SPITCH * 2;    // bytes = 144
static constexpr int TILE_B = 128 * SPB;     // 18432
static constexpr int CONV_SMEM = 4 * TILE_B; // 73728
static constexpr int OPITCH = 132;           // fp32 epilogue pitch

template <int CIN, int COUT, int HIN, int WIN, int STRIDE>
__global__ void __launch_bounds__(256, 2)
convMMA_kernel(const float* __restrict__ in, const __nv_bfloat16* __restrict__ wh,
               const __nv_bfloat16* __restrict__ wl, const float* __restrict__ scale,
               const float* __restrict__ shift, float* __restrict__ out)
{
    constexpr int HO   = (HIN - 1) / STRIDE + 1;
    constexpr int WO   = (WIN - 1) / STRIDE + 1;
    constexpr int MPIX = HO * WO;
    constexpr int NIMG = (MPIX >= 128) ? 1 : (128 / MPIX);
    constexpr int MT   = (MPIX >= 128) ? (MPIX / 128) : 1;
    constexpr int NT   = COUT / 128;
    constexpr int KTOT = 9 * CIN;
    constexpr int CPT  = CIN / 64;
    constexpr int NCH  = 9 * CPT;

    extern __shared__ char smem[];
    const uint32_t sb  = smem_to_u32(smem);
    const uint32_t sAh = sb, sAl = sb + TILE_B, sBh = sb + 2 * TILE_B, sBl = sb + 3 * TILE_B;

    const int tid = threadIdx.x, wid = tid >> 5, lane = tid & 31;
    const int mt  = blockIdx.x / NT;
    const int co0 = (blockIdx.x % NT) * 128;
    const int n0  = blockIdx.y * NIMG;
    const int wm  = wid & 3;      // 4 warps over M (32 rows each)
    const int wn  = wid >> 2;     // 2 warps over N (64 cols each)

    float acc[2][8][4];
#pragma unroll
    for (int a = 0; a < 2; a++)
#pragma unroll
        for (int b = 0; b < 8; b++)
#pragma unroll
            for (int c = 0; c < 4; c++) acc[a][b][c] = 0.f;

    for (int kc = 0; kc < NCH; kc++) {
        if (kc) __syncthreads();
        const int tap = kc / CPT;
        const int ci0 = (kc - tap * CPT) * 64;
        const int dy = tap / 3 - 1, dx = tap % 3 - 1;

        // ---- A tile (im2col + split): 128 rows x 32 u32 ----
#pragma unroll
        for (int it = 0; it < 16; it++) {
            int i  = tid + it * 256;
            int p  = i & 127;
            int cp = i >> 7;
            int g  = mt * 128 + p;
            int img = g / MPIX, pix = g % MPIX;
            int oh = pix / WO, ow = pix % WO;
            int ih = oh * STRIDE + dy, iw = ow * STRIDE + dx;
            int ci = ci0 + cp * 2;
            float v0 = 0.f, v1 = 0.f;
            if ((unsigned)ih < (unsigned)HIN && (unsigned)iw < (unsigned)WIN) {
                const float* ptr =
                    in + (((size_t)(n0 + img) * CIN + ci) * HIN + ih) * WIN + iw;
                v0 = ptr[0];
                v1 = ptr[HIN * WIN];
            }
            __nv_bfloat16 h0 = __float2bfloat16(v0), h1 = __float2bfloat16(v1);
            __nv_bfloat16 l0 = __float2bfloat16(v0 - __bfloat162float(h0));
            __nv_bfloat16 l1 = __float2bfloat16(v1 - __bfloat162float(h1));
            uint32_t o = (uint32_t)p * SPB + (uint32_t)cp * 4u;
            sts32(sAh + o, pack_bf2(h0, h1));
            sts32(sAl + o, pack_bf2(l0, l1));
        }
        // ---- B tile: 128 co-rows x 64 bf16 (16B per thread-iter) ----
#pragma unroll
        for (int it = 0; it < 4; it++) {
            int i   = tid + it * 256;
            int co  = i >> 3;
            int c16 = i & 7;
            size_t eoff = (size_t)(co0 + co) * KTOT + (size_t)kc * 64 + c16 * 8;
            uint4 vh = *reinterpret_cast<const uint4*>(wh + eoff);
            uint4 vl = *reinterpret_cast<const uint4*>(wl + eoff);
            uint32_t o = (uint32_t)co * SPB + (uint32_t)c16 * 16u;
            sts128(sBh + o, vh);
            sts128(sBl + o, vl);
        }
        __syncthreads();

        // ---- consume: 4 k16-steps ----
#pragma unroll
        for (int ks = 0; ks < 4; ks++) {
            const uint32_t acol = (uint32_t)ks * 32u + ((lane >> 4) << 4);
            uint32_t ah[2][4], al2[2][4];
#pragma unroll
            for (int m2 = 0; m2 < 2; m2++) {
                uint32_t arow = (uint32_t)(wm * 32 + m2 * 16 + (lane & 15));
                ldsm_x4(ah[m2],  sAh + arow * SPB + acol);
                ldsm_x4(al2[m2], sAl + arow * SPB + acol);
            }
#pragma unroll
            for (int nt2 = 0; nt2 < 4; nt2++) {
                uint32_t brow = (uint32_t)(wn * 64 + nt2 * 16 +
                                           ((lane >> 4) << 3) + (lane & 7));
                uint32_t bcol = (uint32_t)ks * 32u + (((lane >> 3) & 1) << 4);
                uint32_t bh[4], bl4[4];
                ldsm_x4(bh, sBh + brow * SPB + bcol);
#pragma unroll
                for (int m2 = 0; m2 < 2; m2++) {
                    mma_bf16(acc[m2][nt2 * 2],     ah[m2], bh[0], bh[1]);
                    mma_bf16(acc[m2][nt2 * 2 + 1], ah[m2], bh[2], bh[3]);
                }
                ldsm_x4(bl4, sBl + brow * SPB + bcol);
#pragma unroll
                for (int m2 = 0; m2 < 2; m2++) {
                    mma_bf16(acc[m2][nt2 * 2],     ah[m2], bl4[0], bl4[1]);
                    mma_bf16(acc[m2][nt2 * 2 + 1], ah[m2], bl4[2], bl4[3]);
                    mma_bf16(acc[m2][nt2 * 2],     al2[m2], bh[0], bh[1]);
                    mma_bf16(acc[m2][nt2 * 2 + 1], al2[m2], bh[2], bh[3]);
                }
            }
        }
    }
    __syncthreads();

    // ---- epilogue: transpose through smem, fused affine+relu, coalesced STG
    float* sOut = reinterpret_cast<float*>(smem);
#pragma unroll
    for (int m2 = 0; m2 < 2; m2++) {
#pragma unroll
        for (int nt2 = 0; nt2 < 8; nt2++) {
            int m = wm * 32 + m2 * 16 + (lane >> 2);
            int nn = wn * 64 + nt2 * 8 + (lane & 3) * 2;
            sOut[(size_t)nn * OPITCH + m]           = acc[m2][nt2][0];
            sOut[(size_t)(nn + 1) * OPITCH + m]     = acc[m2][nt2][1];
            sOut[(size_t)nn * OPITCH + m + 8]       = acc[m2][nt2][2];
            sOut[(size_t)(nn + 1) * OPITCH + m + 8] = acc[m2][nt2][3];
        }
    }
    __syncthreads();

    {
        int row  = tid >> 1;          // local co
        int half = tid & 1;
        int co   = co0 + row;
        float s = __ldg(scale + co), t = __ldg(shift + co);
#pragma unroll
        for (int q = 0; q < 16; q++) {
            int m = half * 64 + q * 4;
            float4 v = *reinterpret_cast<float4*>(&sOut[(size_t)row * OPITCH + m]);
            v.x = fmaxf(fmaf(v.x, s, t), 0.f);
            v.y = fmaxf(fmaf(v.y, s, t), 0.f);
            v.z = fmaxf(fmaf(v.z, s, t), 0.f);
            v.w = fmaxf(fmaf(v.w, s, t), 0.f);
            int g = mt * 128 + m;
            int img = g / MPIX, pix = g % MPIX;
            *reinterpret_cast<float4*>(
                &out[((size_t)(n0 + img) * COUT + co) * MPIX + pix]) = v;
        }
    }
}

// ---------------------------------------------------------------------------
// Warp-per-output GEMV for MLPs
// ---------------------------------------------------------------------------
__global__ void warpdot_kernel(const float* __restrict__ X, const float* __restrict__ W,
                               const float* __restrict__ bias, float* __restrict__ Y,
                               int M, int N, int K, int doRelu)
{
    int gw   = (blockIdx.x * blockDim.x + threadIdx.x) >> 5;
    int lane = threadIdx.x & 31;
    if (gw >= M * N) return;
    int m = gw / N, n = gw - m * N;
    const float4* x = (const float4*)(X + (size_t)m * K);
    const float4* w = (const float4*)(W + (size_t)n * K);
    float acc = 0.f;
    int K4 = K >> 2;
    for (int k = lane; k < K4; k += 32) {
        float4 a = x[k], b = w[k];
        acc += a.x * b.x + a.y * b.y + a.z * b.z + a.w * b.w;
    }
#pragma unroll
    for (int o = 16; o; o >>= 1) acc += __shfl_xor_sync(0xffffffffu, acc, o);
    if (lane == 0) {
        float v = acc + bias[n];
        if (doRelu) v = fmaxf(v, 0.f);
        Y[(size_t)m * N + n] = v;
    }
}

// ---------------------------------------------------------------------------
// Attention + softmax -> fuse weights (replicates reference's (N,B) reshape)
// ---------------------------------------------------------------------------
__global__ void attn_kernel(const float* __restrict__ keys, const float* __restrict__ qq,
                            float* __restrict__ wf)
{
    int b = blockIdx.x;
    __shared__ float sA[5][5];
    int warp = threadIdx.x >> 5, lane = threadIdx.x & 31;
    for (int e = warp; e < 25; e += 8) {
        int i = e / 5, j = e - i * 5;
        const float4* kr = (const float4*)(keys + (size_t)(i * 32 + b) * 1024);
        const float4* qr = (const float4*)(qq + (size_t)(j * 32 + b) * 1024);
        float acc = 0.f;
        for (int k = lane; k < 256; k += 32) {
            float4 a = kr[k], c = qr[k];
            acc += a.x * c.x + a.y * c.y + a.z * c.z + a.w * c.w;
        }
#pragma unroll
        for (int o = 16; o; o >>= 1) acc += __shfl_xor_sync(0xffffffffu, acc, o);
        if (lane == 0) sA[i][j] = acc;
    }
    __syncthreads();
    if (threadIdx.x == 0) {
        float w[5] = {0.f, 0.f, 0.f, 0.f, 0.f};
        for (int j = 0; j < 5; j++) {
            float dd[4], mx = -1e30f;
            for (int r = 0; r < 4; r++) {
                dd[r] = (j > r) ? sA[r][j] : sA[r + 1][j];
                mx = fmaxf(mx, dd[r]);
            }
            float s = 0.f;
            for (int r = 0; r < 4; r++) { dd[r] = expf(dd[r] - mx); s += dd[r]; }
            float inv = 1.f / s;
            for (int r = 0; r < 4; r++) {
                int i = (j > r) ? r : r + 1;
                w[i] += dd[r] * inv;
            }
        }
        for (int i = 0; i < 5; i++) wf[b * 5 + i] = w[i] * 0.2f;
    }
}

__global__ void fuse_kernel(const float* __restrict__ bevs, const float* __restrict__ wf,
                            float* __restrict__ out)
{
    const int CHW = 256 * 16 * 16;
    int idx = blockIdx.x * blockDim.x + threadIdx.x;
    if (idx >= 32 * CHW) return;
    int b   = idx / CHW;
    int chw = idx - b * CHW;
    const float* base = bevs + ((size_t)b * 5) * CHW + chw;
    float acc = 0.f;
#pragma unroll
    for (int k = 0; k < 5; k++) acc += wf[b * 5 + k] * base[(size_t)k * CHW];
    out[idx] = acc;
}

// ---------------------------------------------------------------------------
extern "C" void kernel_launch(void* const* d_in, const int* in_sizes, int n_in,
                              void* d_out, int out_size)
{
    (void)in_sizes; (void)n_in; (void)out_size;
    const float* bevs = (const float*)d_in[0];
    const float *cw[5], *cs[5], *ct[5];
    for (int i = 0; i < 5; i++) {
        cw[i] = (const float*)d_in[1 + 3 * i];
        cs[i] = (const float*)d_in[2 + 3 * i];
        ct[i] = (const float*)d_in[3 + 3 * i];
    }
    const float* kw1 = (const float*)d_in[16]; const float* kb1 = (const float*)d_in[17];
    const float* kw2 = (const float*)d_in[18]; const float* kb2 = (const float*)d_in[19];
    const float* kw3 = (const float*)d_in[20]; const float* kb3 = (const float*)d_in[21];
    const float* qw1 = (const float*)d_in[22]; const float* qb1 = (const float*)d_in[23];
    const float* qw2 = (const float*)d_in[24]; const float* qb2 = (const float*)d_in[25];
    const float* qw3 = (const float*)d_in[26]; const float* qb3 = (const float*)d_in[27];
    const float* aw  = (const float*)d_in[28]; const float* ab  = (const float*)d_in[29];
    float* out = (float*)d_out;

    float *b1, *b2, *b3, *b4, *feat, *m1, *m2, *keys, *qrys, *qq, *wf;
    cudaGetSymbolAddress((void**)&b1, g_b1);
    cudaGetSymbolAddress((void**)&b2, g_b2);
    cudaGetSymbolAddress((void**)&b3, g_b3);
    cudaGetSymbolAddress((void**)&b4, g_b4);
    cudaGetSymbolAddress((void**)&feat, g_feat);
    cudaGetSymbolAddress((void**)&m1, g_m1);
    cudaGetSymbolAddress((void**)&m2, g_m2);
    cudaGetSymbolAddress((void**)&keys, g_keys);
    cudaGetSymbolAddress((void**)&qrys, g_qrys);
    cudaGetSymbolAddress((void**)&qq, g_qq);
    cudaGetSymbolAddress((void**)&wf, g_wf);

    __nv_bfloat16 *w1h, *w1l, *w2h, *w2l, *w3h, *w3l, *w4h, *w4l, *w5h, *w5l;
    cudaGetSymbolAddress((void**)&w1h, g_w1h); cudaGetSymbolAddress((void**)&w1l, g_w1l);
    cudaGetSymbolAddress((void**)&w2h, g_w2h); cudaGetSymbolAddress((void**)&w2l, g_w2l);
    cudaGetSymbolAddress((void**)&w3h, g_w3h); cudaGetSymbolAddress((void**)&w3l, g_w3l);
    cudaGetSymbolAddress((void**)&w4h, g_w4h); cudaGetSymbolAddress((void**)&w4l, g_w4l);
    cudaGetSymbolAddress((void**)&w5h, g_w5h); cudaGetSymbolAddress((void**)&w5l, g_w5l);

    cudaFuncSetAttribute(convMMA_kernel<256, 512, 16, 16, 1>,
                         cudaFuncAttributeMaxDynamicSharedMemorySize, CONV_SMEM);
    cudaFuncSetAttribute(convMMA_kernel<512, 256, 16, 16, 1>,
                         cudaFuncAttributeMaxDynamicSharedMemorySize, CONV_SMEM);
    cudaFuncSetAttribute(convMMA_kernel<256, 256, 16, 16, 2>,
                         cudaFuncAttributeMaxDynamicSharedMemorySize, CONV_SMEM);
    cudaFuncSetAttribute(convMMA_kernel<256, 256, 8, 8, 1>,
                         cudaFuncAttributeMaxDynamicSharedMemorySize, CONV_SMEM);
    cudaFuncSetAttribute(convMMA_kernel<256, 256, 8, 8, 2>,
                         cudaFuncAttributeMaxDynamicSharedMemorySize, CONV_SMEM);

    // weight split prep
    wprep_kernel<<<512, 256>>>(cw[0], w1h, w1l, 512, 256);
    wprep_kernel<<<512, 256>>>(cw[1], w2h, w2l, 256, 512);
    wprep_kernel<<<512, 256>>>(cw[2], w3h, w3l, 256, 256);
    wprep_kernel<<<512, 256>>>(cw[3], w4h, w4l, 256, 256);
    wprep_kernel<<<512, 256>>>(cw[4], w5h, w5l, 256, 256);

    // conv stack: grid.x = MT*NT, grid.y = 160/NIMG
    convMMA_kernel<256, 512, 16, 16, 1><<<dim3(2 * 4, 160), 256, CONV_SMEM>>>(
        bevs, w1h, w1l, cs[0], ct[0], b1);
    convMMA_kernel<512, 256, 16, 16, 1><<<dim3(2 * 2, 160), 256, CONV_SMEM>>>(
        b1, w2h, w2l, cs[1], ct[1], b2);
    convMMA_kernel<256, 256, 16, 16, 2><<<dim3(1 * 2, 80), 256, CONV_SMEM>>>(
        b2, w3h, w3l, cs[2], ct[2], b3);
    convMMA_kernel<256, 256, 8, 8, 1><<<dim3(1 * 2, 80), 256, CONV_SMEM>>>(
        b3, w4h, w4l, cs[3], ct[3], b4);
    convMMA_kernel<256, 256, 8, 8, 2><<<dim3(1 * 2, 20), 256, CONV_SMEM>>>(
        b4, w5h, w5l, cs[4], ct[4], feat);

    // MLPs + projection
    auto wd = [&](const float* X, const float* W, const float* B, float* Y,
                  int M, int N, int K, int relu) {
        int blocks = (M * N + 7) / 8;
        warpdot_kernel<<<blocks, 256>>>(X, W, B, Y, M, N, K, relu);
    };
    wd(feat, kw1, kb1, m1,   160,  256, 4096, 1);
    wd(m1,   kw2, kb2, m2,   160,  128,  256, 1);
    wd(m2,   kw3, kb3, keys, 160, 1024,  128, 0);
    wd(feat, qw1, qb1, m1,   160,  256, 4096, 1);
    wd(m1,   qw2, qb2, m2,   160,  128,  256, 1);
    wd(m2,   qw3, qb3, qrys, 160,   32,  128, 0);
    wd(qrys, aw,  ab,  qq,   160, 1024,   32, 0);

    attn_kernel<<<32, 256>>>(keys, qq, wf);
    fuse_kernel<<<(32 * 256 * 16 * 16 + 255) / 256, 256>>>(bevs, wf, out);
}

// round 5
// speedup vs baseline: 4.0568x; 1.5016x over previous
#include <cuda_runtime.h>
#include <cuda_bf16.h>
#include <cstdint>
#include <cstddef>

// ===========================================================================
// Who2com forward — split-bf16 mma.sync implicit-GEMM convs with NHWC
// pre-split activations + cp.async double-buffered pipeline; warptile tail.
// ===========================================================================

__device__ __forceinline__ uint32_t smem_to_u32(const void* p) {
    uint32_t a;
    asm("{ .reg .u64 t; cvta.to.shared.u64 t, %1; cvt.u32.u64 %0, t; }"
        : "=r"(a) : "l"(p));
    return a;
}
__device__ __forceinline__ void ldsm_x4(uint32_t (&r)[4], uint32_t addr) {
    asm volatile("ldmatrix.sync.aligned.m8n8.x4.shared.b16 {%0,%1,%2,%3}, [%4];"
                 : "=r"(r[0]), "=r"(r[1]), "=r"(r[2]), "=r"(r[3]) : "r"(addr));
}
__device__ __forceinline__ void mma_bf16(float (&d)[4], const uint32_t (&a)[4],
                                         uint32_t b0, uint32_t b1) {
    asm volatile(
        "mma.sync.aligned.m16n8k16.row.col.f32.bf16.bf16.f32 "
        "{%0,%1,%2,%3}, {%4,%5,%6,%7}, {%8,%9}, {%0,%1,%2,%3};"
        : "+f"(d[0]), "+f"(d[1]), "+f"(d[2]), "+f"(d[3])
        : "r"(a[0]), "r"(a[1]), "r"(a[2]), "r"(a[3]), "r"(b0), "r"(b1));
}
__device__ __forceinline__ uint32_t pack_bf2(__nv_bfloat16 a, __nv_bfloat16 b) {
    __nv_bfloat162 t = __halves2bfloat162(a, b);
    return *reinterpret_cast<uint32_t*>(&t);
}
__device__ __forceinline__ void cp16(uint32_t dst, const void* src, bool v) {
    asm volatile("cp.async.cg.shared.global [%0], [%1], 16, %2;"
                 :: "r"(dst), "l"(src), "r"(v ? 16u : 0u) : "memory");
}
#define CP_COMMIT() asm volatile("cp.async.commit_group;" ::: "memory")

// ---------------------------------------------------------------------------
// Scratch
// ---------------------------------------------------------------------------
__device__ __align__(16) __nv_bfloat16 g_a0h[(size_t)160 * 256 * 256];
__device__ __align__(16) __nv_bfloat16 g_a0l[(size_t)160 * 256 * 256];
__device__ __align__(16) __nv_bfloat16 g_b1h[(size_t)160 * 256 * 512];
__device__ __align__(16) __nv_bfloat16 g_b1l[(size_t)160 * 256 * 512];
__device__ __align__(16) __nv_bfloat16 g_b2h[(size_t)160 * 256 * 256];
__device__ __align__(16) __nv_bfloat16 g_b2l[(size_t)160 * 256 * 256];
__device__ __align__(16) __nv_bfloat16 g_b3h[(size_t)160 * 64 * 256];
__device__ __align__(16) __nv_bfloat16 g_b3l[(size_t)160 * 64 * 256];
__device__ __align__(16) __nv_bfloat16 g_b4h[(size_t)160 * 64 * 256];
__device__ __align__(16) __nv_bfloat16 g_b4l[(size_t)160 * 64 * 256];
__device__ float g_feat[(size_t)160 * 4096];
__device__ float g_m1[160 * 256];
__device__ float g_m2[160 * 128];
__device__ float g_keys[160 * 1024];
__device__ float g_qrys[160 * 32];
__device__ float g_qq[160 * 1024];
__device__ float g_wf[32 * 5];
__device__ __align__(16) __nv_bfloat16 g_w1h[512 * 2304], g_w1l[512 * 2304];
__device__ __align__(16) __nv_bfloat16 g_w2h[256 * 4608], g_w2l[256 * 4608];
__device__ __align__(16) __nv_bfloat16 g_w3h[256 * 2304], g_w3l[256 * 2304];
__device__ __align__(16) __nv_bfloat16 g_w4h[256 * 2304], g_w4l[256 * 2304];
__device__ __align__(16) __nv_bfloat16 g_w5h[256 * 2304], g_w5l[256 * 2304];

// ---------------------------------------------------------------------------
// Weight prep: src[co][ci][kh][kw] -> hi/lo bf16 at [co][(kh*3+kw)*CIN + ci]
// ---------------------------------------------------------------------------
__global__ void wprep_kernel(const float* __restrict__ w, __nv_bfloat16* __restrict__ hi,
                             __nv_bfloat16* __restrict__ lo, int COUT, int CIN)
{
    int total = COUT * CIN * 9;
    for (int idx = blockIdx.x * blockDim.x + threadIdx.x; idx < total;
         idx += gridDim.x * blockDim.x) {
        int co = idx / (CIN * 9);
        int rem = idx - co * (CIN * 9);
        int ci = rem / 9, tap = rem - ci * 9;
        float v = w[idx];
        __nv_bfloat16 h = __float2bfloat16(v);
        __nv_bfloat16 l = __float2bfloat16(v - __bfloat162float(h));
        size_t d = (size_t)co * (CIN * 9) + tap * CIN + ci;
        hi[d] = h; lo[d] = l;
    }
}

// bevs NCHW fp32 -> NHWC hi/lo bf16.  block: (n, ciTile of 32); 256 thr.
__global__ void actsplit_kernel(const float* __restrict__ in,
                                __nv_bfloat16* __restrict__ oh,
                                __nv_bfloat16* __restrict__ ol)
{
    __shared__ float s[32][257];
    int n = blockIdx.x, c0 = blockIdx.y * 32;
    int tid = threadIdx.x;
#pragma unroll
    for (int it = 0; it < 32; it++)
        s[it][tid] = in[((size_t)n * 256 + c0 + it) * 256 + tid];
    __syncthreads();
    int ci = tid & 31, p0 = tid >> 5;
#pragma unroll
    for (int pp = 0; pp < 32; pp++) {
        int pix = p0 + pp * 8;
        float v = s[ci][pix];
        __nv_bfloat16 h = __float2bfloat16(v);
        __nv_bfloat16 l = __float2bfloat16(v - __bfloat162float(h));
        size_t o = ((size_t)n * 256 + pix) * 256 + c0 + ci;
        oh[o] = h; ol[o] = l;
    }
}

// ---------------------------------------------------------------------------
// Implicit-GEMM conv3x3 (pad=1) + affine + ReLU, split-bf16 mma.sync.
// Inputs/outputs NHWC hi/lo bf16 (OUTMODE 0) or fp32 CHW feats (OUTMODE 1).
// Block: 128 pixels x 128 cout, 256 thr, K-chunks of 64, cp.async x2 stages.
// ---------------------------------------------------------------------------
static constexpr int SPB     = 144;           // bytes per smem row (72 bf16)
static constexpr int TILE_B  = 128 * SPB;     // 18432
static constexpr int STAGE_B = 4 * TILE_B;    // 73728
static constexpr int CONV_SMEM = 2 * STAGE_B; // 147456
static constexpr int OPITCH  = 132;

template <int CIN, int COUT, int HIN, int WIN, int STRIDE, int OUTMODE>
__global__ void __launch_bounds__(256, 1)
convMMA_kernel(const __nv_bfloat16* __restrict__ aH, const __nv_bfloat16* __restrict__ aL,
               const __nv_bfloat16* __restrict__ wH, const __nv_bfloat16* __restrict__ wL,
               const float* __restrict__ scale, const float* __restrict__ shift,
               __nv_bfloat16* __restrict__ oH, __nv_bfloat16* __restrict__ oL,
               float* __restrict__ oF)
{
    constexpr int HO   = (HIN - 1) / STRIDE + 1;
    constexpr int WO   = (WIN - 1) / STRIDE + 1;
    constexpr int MPIX = HO * WO;
    constexpr int NIMG = (MPIX >= 128) ? 1 : (128 / MPIX);
    constexpr int NT   = COUT / 128;
    constexpr int KTOT = 9 * CIN;
    constexpr int CPT  = CIN / 64;
    constexpr int NCH  = 9 * CPT;

    extern __shared__ char smem[];
    const uint32_t sb = smem_to_u32(smem);

    const int tid = threadIdx.x, wid = tid >> 5, lane = tid & 31;
    const int mt  = blockIdx.x / NT;
    const int co0 = (blockIdx.x % NT) * 128;
    const int n0  = blockIdx.y * NIMG;
    const int wm  = wid & 3;
    const int wn  = wid >> 2;

    auto issue = [&](int c, int s) {
        const uint32_t st = sb + (uint32_t)s * STAGE_B;
        const int tap = c / CPT;
        const int ci0 = (c - tap * CPT) * 64;
        const int dy = tap / 3 - 1, dx = tap % 3 - 1;
        const int seg = tid & 7;
#pragma unroll
        for (int it = 0; it < 4; it++) {
            const int row = (tid >> 3) + 32 * it;
            // ---- A (activations NHWC) ----
            int g = mt * 128 + row;
            int img = g / MPIX, pix = g % MPIX;
            int oh = pix / WO, ow = pix - oh * WO;
            int ih = oh * STRIDE + dy, iw = ow * STRIDE + dx;
            bool v = ((unsigned)ih < (unsigned)HIN) && ((unsigned)iw < (unsigned)WIN);
            int ihs = v ? ih : 0, iws = v ? iw : 0;
            size_t aoff = (((size_t)(n0 + img) * HIN + ihs) * WIN + iws) * CIN
                          + ci0 + seg * 8;
            uint32_t ad = st + (uint32_t)row * SPB + seg * 16;
            cp16(ad, aH + aoff, v);
            cp16(ad + TILE_B, aL + aoff, v);
            // ---- B (weights) ----
            size_t woff = (size_t)(co0 + row) * KTOT + (size_t)c * 64 + seg * 8;
            uint32_t bd = st + 2 * TILE_B + (uint32_t)row * SPB + seg * 16;
            cp16(bd, wH + woff, true);
            cp16(bd + TILE_B, wL + woff, true);
        }
        CP_COMMIT();
    };

    float acc[2][8][4];
#pragma unroll
    for (int a = 0; a < 2; a++)
#pragma unroll
        for (int b = 0; b < 8; b++)
#pragma unroll
            for (int c = 0; c < 4; c++) acc[a][b][c] = 0.f;

    issue(0, 0);
    for (int c = 0; c < NCH; c++) {
        const int s = c & 1;
        if (c + 1 < NCH) {
            issue(c + 1, s ^ 1);
            asm volatile("cp.async.wait_group 1;" ::: "memory");
        } else {
            asm volatile("cp.async.wait_group 0;" ::: "memory");
        }
        __syncthreads();

        const uint32_t sAh = sb + (uint32_t)s * STAGE_B;
        const uint32_t sAl = sAh + TILE_B, sBh = sAh + 2 * TILE_B, sBl = sAh + 3 * TILE_B;
#pragma unroll
        for (int ks = 0; ks < 4; ks++) {
            const uint32_t acol = (uint32_t)ks * 32u + ((lane >> 4) << 4);
            uint32_t ah[2][4], al2[2][4];
#pragma unroll
            for (int m2 = 0; m2 < 2; m2++) {
                uint32_t arow = (uint32_t)(wm * 32 + m2 * 16 + (lane & 15));
                ldsm_x4(ah[m2],  sAh + arow * SPB + acol);
                ldsm_x4(al2[m2], sAl + arow * SPB + acol);
            }
#pragma unroll
            for (int nt2 = 0; nt2 < 4; nt2++) {
                uint32_t brow = (uint32_t)(wn * 64 + nt2 * 16 +
                                           ((lane >> 4) << 3) + (lane & 7));
                uint32_t bcol = (uint32_t)ks * 32u + (((lane >> 3) & 1) << 4);
                uint32_t bh[4], bl4[4];
                ldsm_x4(bh, sBh + brow * SPB + bcol);
#pragma unroll
                for (int m2 = 0; m2 < 2; m2++) {
                    mma_bf16(acc[m2][nt2 * 2],     ah[m2], bh[0], bh[1]);
                    mma_bf16(acc[m2][nt2 * 2 + 1], ah[m2], bh[2], bh[3]);
                }
                ldsm_x4(bl4, sBl + brow * SPB + bcol);
#pragma unroll
                for (int m2 = 0; m2 < 2; m2++) {
                    mma_bf16(acc[m2][nt2 * 2],     ah[m2], bl4[0], bl4[1]);
                    mma_bf16(acc[m2][nt2 * 2 + 1], ah[m2], bl4[2], bl4[3]);
                    mma_bf16(acc[m2][nt2 * 2],     al2[m2], bh[0], bh[1]);
                    mma_bf16(acc[m2][nt2 * 2 + 1], al2[m2], bh[2], bh[3]);
                }
            }
        }
        __syncthreads();
    }

    if (OUTMODE == 0) {
        // ---- NHWC hi/lo epilogue: direct from fragments ----
#pragma unroll
        for (int m2 = 0; m2 < 2; m2++) {
            int mA = wm * 32 + m2 * 16 + (lane >> 2);
            int gA = mt * 128 + mA;
            int gB = gA + 8;
            size_t rowA = ((size_t)(n0 + gA / MPIX) * MPIX + gA % MPIX) * COUT;
            size_t rowB = ((size_t)(n0 + gB / MPIX) * MPIX + gB % MPIX) * COUT;
#pragma unroll
            for (int nt2 = 0; nt2 < 8; nt2++) {
                int co = co0 + wn * 64 + nt2 * 8 + (lane & 3) * 2;
                float s0 = __ldg(scale + co), s1 = __ldg(scale + co + 1);
                float t0 = __ldg(shift + co), t1 = __ldg(shift + co + 1);
                float v0 = fmaxf(fmaf(acc[m2][nt2][0], s0, t0), 0.f);
                float v1 = fmaxf(fmaf(acc[m2][nt2][1], s1, t1), 0.f);
                float v2 = fmaxf(fmaf(acc[m2][nt2][2], s0, t0), 0.f);
                float v3 = fmaxf(fmaf(acc[m2][nt2][3], s1, t1), 0.f);
                __nv_bfloat16 h0 = __float2bfloat16(v0), h1 = __float2bfloat16(v1);
                __nv_bfloat16 h2 = __float2bfloat16(v2), h3 = __float2bfloat16(v3);
                __nv_bfloat16 l0 = __float2bfloat16(v0 - __bfloat162float(h0));
                __nv_bfloat16 l1 = __float2bfloat16(v1 - __bfloat162float(h1));
                __nv_bfloat16 l2 = __float2bfloat16(v2 - __bfloat162float(h2));
                __nv_bfloat16 l3 = __float2bfloat16(v3 - __bfloat162float(h3));
                *reinterpret_cast<uint32_t*>(oH + rowA + co) = pack_bf2(h0, h1);
                *reinterpret_cast<uint32_t*>(oL + rowA + co) = pack_bf2(l0, l1);
                *reinterpret_cast<uint32_t*>(oH + rowB + co) = pack_bf2(h2, h3);
                *reinterpret_cast<uint32_t*>(oL + rowB + co) = pack_bf2(l2, l3);
            }
        }
    } else {
        // ---- CHW fp32 epilogue (conv5 -> feats): transpose via smem ----
        float* sOut = reinterpret_cast<float*>(smem);
#pragma unroll
        for (int m2 = 0; m2 < 2; m2++) {
#pragma unroll
            for (int nt2 = 0; nt2 < 8; nt2++) {
                int m = wm * 32 + m2 * 16 + (lane >> 2);
                int nn = wn * 64 + nt2 * 8 + (lane & 3) * 2;
                sOut[(size_t)nn * OPITCH + m]           = acc[m2][nt2][0];
                sOut[(size_t)(nn + 1) * OPITCH + m]     = acc[m2][nt2][1];
                sOut[(size_t)nn * OPITCH + m + 8]       = acc[m2][nt2][2];
                sOut[(size_t)(nn + 1) * OPITCH + m + 8] = acc[m2][nt2][3];
            }
        }
        __syncthreads();
        int row = tid >> 1, half = tid & 1;
        int co = co0 + row;
        float s = __ldg(scale + co), t = __ldg(shift + co);
#pragma unroll
        for (int q = 0; q < 16; q++) {
            int m = half * 64 + q * 4;
            float4 v = *reinterpret_cast<float4*>(&sOut[(size_t)row * OPITCH + m]);
            v.x = fmaxf(fmaf(v.x, s, t), 0.f);
            v.y = fmaxf(fmaf(v.y, s, t), 0.f);
            v.z = fmaxf(fmaf(v.z, s, t), 0.f);
            v.w = fmaxf(fmaf(v.w, s, t), 0.f);
            int g = mt * 128 + m;
            int img = g / MPIX, pix = g % MPIX;
            *reinterpret_cast<float4*>(
                &oF[((size_t)(n0 + img) * COUT + co) * MPIX + pix]) = v;
        }
    }
}

// ---------------------------------------------------------------------------
// Warp-tile GEMV: each warp computes a 4m x 8n tile of Y = X.W^T + b.
// ---------------------------------------------------------------------------
__global__ void warptile_kernel(const float* __restrict__ X, const float* __restrict__ W,
                                const float* __restrict__ bias, float* __restrict__ Y,
                                int M, int N, int K, int doRelu)
{
    int gw   = (blockIdx.x * blockDim.x + threadIdx.x) >> 5;
    int lane = threadIdx.x & 31;
    int nW = N >> 3;
    int mtile = gw / nW, ntile = gw - mtile * nW;
    if (mtile * 4 >= M) return;
    const float* x0 = X + (size_t)(mtile * 4) * K;
    const float* w0 = W + (size_t)(ntile * 8) * K;
    float acc[4][8];
#pragma unroll
    for (int i = 0; i < 4; i++)
#pragma unroll
        for (int j = 0; j < 8; j++) acc[i][j] = 0.f;
    for (int k = lane; k < K; k += 32) {
        float xv[4], wv[8];
#pragma unroll
        for (int i = 0; i < 4; i++) xv[i] = x0[(size_t)i * K + k];
#pragma unroll
        for (int j = 0; j < 8; j++) wv[j] = w0[(size_t)j * K + k];
#pragma unroll
        for (int i = 0; i < 4; i++)
#pragma unroll
            for (int j = 0; j < 8; j++) acc[i][j] = fmaf(xv[i], wv[j], acc[i][j]);
    }
#pragma unroll
    for (int o = 16; o; o >>= 1)
#pragma unroll
        for (int i = 0; i < 4; i++)
#pragma unroll
            for (int j = 0; j < 8; j++)
                acc[i][j] += __shfl_xor_sync(0xffffffffu, acc[i][j], o);
    int i = lane >> 3, j = lane & 7;
    float v = acc[i][j] + bias[ntile * 8 + j];
    if (doRelu) v = fmaxf(v, 0.f);
    Y[(size_t)(mtile * 4 + i) * N + ntile * 8 + j] = v;
}

// ---------------------------------------------------------------------------
// Attention + softmax -> fuse weights; final fuse.
// ---------------------------------------------------------------------------
__global__ void attn_kernel(const float* __restrict__ keys, const float* __restrict__ qq,
                            float* __restrict__ wf)
{
    int b = blockIdx.x;
    __shared__ float sA[5][5];
    int warp = threadIdx.x >> 5, lane = threadIdx.x & 31;
    for (int e = warp; e < 25; e += 8) {
        int i = e / 5, j = e - i * 5;
        const float4* kr = (const float4*)(keys + (size_t)(i * 32 + b) * 1024);
        const float4* qr = (const float4*)(qq + (size_t)(j * 32 + b) * 1024);
        float acc = 0.f;
        for (int k = lane; k < 256; k += 32) {
            float4 a = kr[k], c = qr[k];
            acc += a.x * c.x + a.y * c.y + a.z * c.z + a.w * c.w;
        }
#pragma unroll
        for (int o = 16; o; o >>= 1) acc += __shfl_xor_sync(0xffffffffu, acc, o);
        if (lane == 0) sA[i][j] = acc;
    }
    __syncthreads();
    if (threadIdx.x == 0) {
        float w[5] = {0.f, 0.f, 0.f, 0.f, 0.f};
        for (int j = 0; j < 5; j++) {
            float dd[4], mx = -1e30f;
            for (int r = 0; r < 4; r++) {
                dd[r] = (j > r) ? sA[r][j] : sA[r + 1][j];
                mx = fmaxf(mx, dd[r]);
            }
            float s = 0.f;
            for (int r = 0; r < 4; r++) { dd[r] = expf(dd[r] - mx); s += dd[r]; }
            float inv = 1.f / s;
            for (int r = 0; r < 4; r++) {
                int i = (j > r) ? r : r + 1;
                w[i] += dd[r] * inv;
            }
        }
        for (int i = 0; i < 5; i++) wf[b * 5 + i] = w[i] * 0.2f;
    }
}

__global__ void fuse_kernel(const float* __restrict__ bevs, const float* __restrict__ wf,
                            float* __restrict__ out)
{
    const int CHW = 256 * 16 * 16;
    int idx = blockIdx.x * blockDim.x + threadIdx.x;
    if (idx >= 32 * CHW) return;
    int b   = idx / CHW;
    int chw = idx - b * CHW;
    const float* base = bevs + ((size_t)b * 5) * CHW + chw;
    float acc = 0.f;
#pragma unroll
    for (int k = 0; k < 5; k++) acc += wf[b * 5 + k] * base[(size_t)k * CHW];
    out[idx] = acc;
}

// ---------------------------------------------------------------------------
extern "C" void kernel_launch(void* const* d_in, const int* in_sizes, int n_in,
                              void* d_out, int out_size)
{
    (void)in_sizes; (void)n_in; (void)out_size;
    const float* bevs = (const float*)d_in[0];
    const float *cw[5], *cs[5], *ct[5];
    for (int i = 0; i < 5; i++) {
        cw[i] = (const float*)d_in[1 + 3 * i];
        cs[i] = (const float*)d_in[2 + 3 * i];
        ct[i] = (const float*)d_in[3 + 3 * i];
    }
    const float* kw1 = (const float*)d_in[16]; const float* kb1 = (const float*)d_in[17];
    const float* kw2 = (const float*)d_in[18]; const float* kb2 = (const float*)d_in[19];
    const float* kw3 = (const float*)d_in[20]; const float* kb3 = (const float*)d_in[21];
    const float* qw1 = (const float*)d_in[22]; const float* qb1 = (const float*)d_in[23];
    const float* qw2 = (const float*)d_in[24]; const float* qb2 = (const float*)d_in[25];
    const float* qw3 = (const float*)d_in[26]; const float* qb3 = (const float*)d_in[27];
    const float* aw  = (const float*)d_in[28]; const float* ab  = (const float*)d_in[29];
    float* out = (float*)d_out;

    __nv_bfloat16 *a0h, *a0l, *b1h, *b1l, *b2h, *b2l, *b3h, *b3l, *b4h, *b4l;
    cudaGetSymbolAddress((void**)&a0h, g_a0h); cudaGetSymbolAddress((void**)&a0l, g_a0l);
    cudaGetSymbolAddress((void**)&b1h, g_b1h); cudaGetSymbolAddress((void**)&b1l, g_b1l);
    cudaGetSymbolAddress((void**)&b2h, g_b2h); cudaGetSymbolAddress((void**)&b2l, g_b2l);
    cudaGetSymbolAddress((void**)&b3h, g_b3h); cudaGetSymbolAddress((void**)&b3l, g_b3l);
    cudaGetSymbolAddress((void**)&b4h, g_b4h); cudaGetSymbolAddress((void**)&b4l, g_b4l);
    float *feat, *m1, *m2, *keys, *qrys, *qq, *wf;
    cudaGetSymbolAddress((void**)&feat, g_feat);
    cudaGetSymbolAddress((void**)&m1, g_m1);
    cudaGetSymbolAddress((void**)&m2, g_m2);
    cudaGetSymbolAddress((void**)&keys, g_keys);
    cudaGetSymbolAddress((void**)&qrys, g_qrys);
    cudaGetSymbolAddress((void**)&qq, g_qq);
    cudaGetSymbolAddress((void**)&wf, g_wf);
    __nv_bfloat16 *w1h, *w1l, *w2h, *w2l, *w3h, *w3l, *w4h, *w4l, *w5h, *w5l;
    cudaGetSymbolAddress((void**)&w1h, g_w1h); cudaGetSymbolAddress((void**)&w1l, g_w1l);
    cudaGetSymbolAddress((void**)&w2h, g_w2h); cudaGetSymbolAddress((void**)&w2l, g_w2l);
    cudaGetSymbolAddress((void**)&w3h, g_w3h); cudaGetSymbolAddress((void**)&w3l, g_w3l);
    cudaGetSymbolAddress((void**)&w4h, g_w4h); cudaGetSymbolAddress((void**)&w4l, g_w4l);
    cudaGetSymbolAddress((void**)&w5h, g_w5h); cudaGetSymbolAddress((void**)&w5l, g_w5l);

    cudaFuncSetAttribute(convMMA_kernel<256, 512, 16, 16, 1, 0>,
                         cudaFuncAttributeMaxDynamicSharedMemorySize, CONV_SMEM);
    cudaFuncSetAttribute(convMMA_kernel<512, 256, 16, 16, 1, 0>,
                         cudaFuncAttributeMaxDynamicSharedMemorySize, CONV_SMEM);
    cudaFuncSetAttribute(convMMA_kernel<256, 256, 16, 16, 2, 0>,
                         cudaFuncAttributeMaxDynamicSharedMemorySize, CONV_SMEM);
    cudaFuncSetAttribute(convMMA_kernel<256, 256, 8, 8, 1, 0>,
                         cudaFuncAttributeMaxDynamicSharedMemorySize, CONV_SMEM);
    cudaFuncSetAttribute(convMMA_kernel<256, 256, 8, 8, 2, 1>,
                         cudaFuncAttributeMaxDynamicSharedMemorySize, CONV_SMEM);

    // prep: weight splits + bevs NCHW->NHWC split
    wprep_kernel<<<512, 256>>>(cw[0], w1h, w1l, 512, 256);
    wprep_kernel<<<512, 256>>>(cw[1], w2h, w2l, 256, 512);
    wprep_kernel<<<512, 256>>>(cw[2], w3h, w3l, 256, 256);
    wprep_kernel<<<512, 256>>>(cw[3], w4h, w4l, 256, 256);
    wprep_kernel<<<512, 256>>>(cw[4], w5h, w5l, 256, 256);
    actsplit_kernel<<<dim3(160, 8), 256>>>(bevs, a0h, a0l);

    // conv stack
    convMMA_kernel<256, 512, 16, 16, 1, 0><<<dim3(8, 160), 256, CONV_SMEM>>>(
        a0h, a0l, w1h, w1l, cs[0], ct[0], b1h, b1l, nullptr);
    convMMA_kernel<512, 256, 16, 16, 1, 0><<<dim3(4, 160), 256, CONV_SMEM>>>(
        b1h, b1l, w2h, w2l, cs[1], ct[1], b2h, b2l, nullptr);
    convMMA_kernel<256, 256, 16, 16, 2, 0><<<dim3(2, 80), 256, CONV_SMEM>>>(
        b2h, b2l, w3h, w3l, cs[2], ct[2], b3h, b3l, nullptr);
    convMMA_kernel<256, 256, 8, 8, 1, 0><<<dim3(2, 80), 256, CONV_SMEM>>>(
        b3h, b3l, w4h, w4l, cs[3], ct[3], b4h, b4l, nullptr);
    convMMA_kernel<256, 256, 8, 8, 2, 1><<<dim3(2, 20), 256, CONV_SMEM>>>(
        b4h, b4l, w5h, w5l, cs[4], ct[4], nullptr, nullptr, feat);

    // MLPs + projection
    auto wt = [&](const float* X, const float* W, const float* B, float* Y,
                  int M, int N, int K, int relu) {
        int warps = (M / 4) * (N / 8);
        warptile_kernel<<<(warps + 7) / 8, 256>>>(X, W, B, Y, M, N, K, relu);
    };
    wt(feat, kw1, kb1, m1,   160,  256, 4096, 1);
    wt(m1,   kw2, kb2, m2,   160,  128,  256, 1);
    wt(m2,   kw3, kb3, keys, 160, 1024,  128, 0);
    wt(feat, qw1, qb1, m1,   160,  256, 4096, 1);
    wt(m1,   qw2, qb2, m2,   160,  128,  256, 1);
    wt(m2,   qw3, qb3, qrys, 160,   32,  128, 0);
    wt(qrys, aw,  ab,  qq,   160, 1024,   32, 0);

    attn_kernel<<<32, 256>>>(keys, qq, wf);
    fuse_kernel<<<(32 * 256 * 16 * 16 + 255) / 256, 256>>>(bevs, wf, out);
}